// round 2
// baseline (speedup 1.0000x reference)
#include <cuda_runtime.h>

typedef unsigned long long u64;

#define BM 128
#define BN 128
#define BK 16
#define NTHREADS 256

// anchors per level: {aw0,ah0,aw1,ah1,aw2,ah2}
__constant__ float g_anch[3][6] = {
    {10.f, 13.f, 16.f, 30.f, 33.f, 23.f},
    {30.f, 61.f, 62.f, 45.f, 59.f, 119.f},
    {116.f, 90.f, 156.f, 198.f, 373.f, 326.f}
};

__device__ __forceinline__ u64 dup2(float x) {
    u64 r;
    asm("mov.b64 %0, {%1, %1};" : "=l"(r) : "f"(x));
    return r;
}
__device__ __forceinline__ void fma2(u64 &c, u64 a, u64 b) {
    asm("fma.rn.f32x2 %0, %1, %2, %0;" : "+l"(c) : "l"(a), "l"(b));
}
__device__ __forceinline__ float2 unpk(u64 v) {
    float lo, hi;
    asm("mov.b64 {%0, %1}, %2;" : "=f"(lo), "=f"(hi) : "l"(v));
    return make_float2(lo, hi);
}
__device__ __forceinline__ float sigm(float x) { return 1.f / (1.f + __expf(-x)); }

// One GEMM tile (BM x BN) of P = W (267 x C) * X_b (C x HW), fused decode epilogue.
// Accumulators are f32x2-packed along M: acc[ip][j] holds rows (mbase+2ip, mbase+2ip+1), col j.
template<int C, int HW, int NX>
__device__ __forceinline__ void level_gemm(
    const float* __restrict__ X, const float* __restrict__ W,
    float* __restrict__ Out,
    float (&As)[BK][BM + 4], float (&Bs)[BK][BN], const float* sBias,
    int bat, int mt, int nt, float stride_px, int lvl, int loff)
{
    const int tid = threadIdx.x;
    const int tm = tid >> 4;        // 0..15 -> 8 M rows each
    const int tn = tid & 15;        // 0..15 -> 8 N cols each
    const int m0 = mt * BM;
    const int n0 = nt * BN;
    const float* Xb = X + (size_t)bat * C * HW;

    u64 acc[4][8];
#pragma unroll
    for (int i = 0; i < 4; ++i)
#pragma unroll
        for (int j = 0; j < 8; ++j) acc[i][j] = 0ull;

    // tile-load assignments
    const int wm = tid >> 1;              // 0..127 : M row of W tile
    const int wk = (tid & 1) * 8;         // 0 or 8 : k offset (8 floats)
    const int xr = tid >> 4;              // 0..15  : k row of X tile
    const int xc = (tid & 15) * 8;        // 0..120 : n offset (8 floats)
    const int gm = m0 + wm;
    const int gn = n0 + xc;

    for (int k0 = 0; k0 < C; k0 += BK) {
        float4 w0v = make_float4(0.f, 0.f, 0.f, 0.f), w1v = w0v;
        if (gm < 267) {
            const float* wp = W + (size_t)gm * C + (k0 + wk);
            w0v = *(const float4*)wp;
            w1v = *(const float4*)(wp + 4);
        }
        float4 x0v = make_float4(0.f, 0.f, 0.f, 0.f), x1v = x0v;
        if (gn < HW) {  // gn multiple of 8, HW multiple of 8 -> whole 8-float run in-bounds
            const float* xp = Xb + (size_t)(k0 + xr) * HW + gn;
            x0v = *(const float4*)xp;
            x1v = *(const float4*)(xp + 4);
        }
        // store W transposed: As[k][m]
        As[wk + 0][wm] = w0v.x; As[wk + 1][wm] = w0v.y;
        As[wk + 2][wm] = w0v.z; As[wk + 3][wm] = w0v.w;
        As[wk + 4][wm] = w1v.x; As[wk + 5][wm] = w1v.y;
        As[wk + 6][wm] = w1v.z; As[wk + 7][wm] = w1v.w;
        *(float4*)&Bs[xr][xc]     = x0v;
        *(float4*)&Bs[xr][xc + 4] = x1v;
        __syncthreads();

#pragma unroll
        for (int k = 0; k < BK; ++k) {
            const float* ap = &As[k][tm * 8];           // 16B aligned (pad=4)
            ulonglong2 aa = *(const ulonglong2*)ap;     // rows m..m+3 as 2 packed pairs
            ulonglong2 ab = *(const ulonglong2*)(ap + 4);
            float4 bq0 = *(const float4*)&Bs[k][tn * 8];
            float4 bq1 = *(const float4*)&Bs[k][tn * 8 + 4];
            float bf[8] = {bq0.x, bq0.y, bq0.z, bq0.w, bq1.x, bq1.y, bq1.z, bq1.w};
#pragma unroll
            for (int j = 0; j < 8; ++j) {
                u64 bd = dup2(bf[j]);
                fma2(acc[0][j], aa.x, bd);
                fma2(acc[1][j], aa.y, bd);
                fma2(acc[2][j], ab.x, bd);
                fma2(acc[3][j], ab.y, bd);
            }
        }
        __syncthreads();
    }

    // ---- fused decode epilogue ----
    const int mbase = m0 + tm * 8;
#pragma unroll
    for (int ip = 0; ip < 4; ++ip) {
#pragma unroll
        for (int h = 0; h < 2; ++h) {
            const int o = mbase + ip * 2 + h;
            if (o >= 267) continue;
            const int ai = o / 89;
            const int e  = o - ai * 89;
            const float bv = sBias[o];
            float anc = 0.f;
            if (e == 2) anc = g_anch[lvl][ai * 2];
            if (e == 3) anc = g_anch[lvl][ai * 2 + 1];
            const size_t rowbase = (size_t)bat * 25200 + (size_t)loff + (size_t)ai * HW;
#pragma unroll
            for (int j = 0; j < 8; ++j) {
                const int n = n0 + tn * 8 + j;
                if (HW % BN != 0) { if (n >= HW) continue; }
                float2 p = unpk(acc[ip][j]);
                float v = (h ? p.y : p.x) + bv;
                float res;
                if (e == 0)              res = (sigm(v) + (float)(n % NX)) * stride_px;
                else if (e == 1)         res = (sigm(v) + (float)(n / NX)) * stride_px;
                else if (e == 2 || e == 3) res = __expf(v) * anc;
                else                     res = sigm(v);
                Out[(rowbase + (size_t)n) * 89 + e] = res;
            }
        }
    }
}

// Level tile counts along N: L0: 6400/128=50, L1: ceil(1600/128)=13, L2: ceil(400/128)=4 -> 67
__global__ void __launch_bounds__(NTHREADS, 2)
detect_fused(const float* __restrict__ x0, const float* __restrict__ w0, const float* __restrict__ b0,
             const float* __restrict__ x1, const float* __restrict__ w1, const float* __restrict__ b1,
             const float* __restrict__ x2, const float* __restrict__ w2, const float* __restrict__ b2,
             float* __restrict__ out)
{
    __shared__ float As[BK][BM + 4];
    __shared__ float Bs[BK][BN];
    __shared__ float sBias[272];

    const int bat = blockIdx.z;
    const int mt  = blockIdx.y;
    const int xt  = blockIdx.x;

    const float* bias = (xt < 50) ? b0 : ((xt < 63) ? b1 : b2);
    for (int i = threadIdx.x; i < 272; i += NTHREADS)
        sBias[i] = (i < 267) ? bias[i] : 0.f;
    // first __syncthreads inside level_gemm orders sBias before its epilogue use

    if (xt < 50)
        level_gemm<256, 6400, 80>(x0, w0, out, As, Bs, sBias, bat, mt, xt,       8.f, 0, 0);
    else if (xt < 63)
        level_gemm<512, 1600, 40>(x1, w1, out, As, Bs, sBias, bat, mt, xt - 50, 16.f, 1, 19200);
    else
        level_gemm<1024, 400, 20>(x2, w2, out, As, Bs, sBias, bat, mt, xt - 63, 32.f, 2, 24000);
}

extern "C" void kernel_launch(void* const* d_in, const int* in_sizes, int n_in,
                              void* d_out, int out_size)
{
    // Resolve inputs by element count (robust to metadata ordering).
    const float *x0 = 0, *x1 = 0, *x2 = 0, *w0 = 0, *w1 = 0, *w2 = 0;
    const float* bs[3] = {0, 0, 0};
    int nb = 0;
    for (int i = 0; i < n_in; ++i) {
        const float* p = (const float*)d_in[i];
        switch (in_sizes[i]) {
            case 13107200: x0 = p; break;  // 8*256*80*80
            case 6553600:  x1 = p; break;  // 8*512*40*40
            case 3276800:  x2 = p; break;  // 8*1024*20*20
            case 68352:    w0 = p; break;  // 267*256
            case 136704:   w1 = p; break;  // 267*512
            case 273408:   w2 = p; break;  // 267*1024
            case 267:      if (nb < 3) bs[nb++] = p; break;  // b0, b1, b2 in order
            default: break;
        }
    }
    dim3 grid(67, 3, 8);
    dim3 block(NTHREADS);
    detect_fused<<<grid, block>>>(x0, w0, bs[0], x1, w1, bs[1], x2, w2, bs[2],
                                  (float*)d_out);
}